// round 16
// baseline (speedup 1.0000x reference)
#include <cuda_runtime.h>
#include <cuda_fp16.h>
#include <cstdint>

#define NV 100000      // vertices
#define ME 50000       // hyperedges
#define KH 8           // hyperedge size
#define DD 128         // feature dim
#define ASTRIDE 136    // smem A row stride (halves)

// ---------------- scratch (no allocs allowed) ----------------
__device__ __half g_Yh [(size_t)NV * DD];   // Y hi (fp16)
__device__ __half g_Yl [(size_t)NV * DD];   // Y lo (fp16 residual)
__device__ __half g_acc[(size_t)NV * DD];   // fp16 neighbor accumulator
__device__ float  g_deg [NV];
__device__ int    g_pos[ME];                // ui | (vi<<8)
__device__ __half g_Wph[16384];             // W hi, mma B-fragment layout
__device__ __half g_Wpl[16384];             // W lo, mma B-fragment layout

__device__ __forceinline__ void red2h(__half* p, uint32_t a, uint32_t b) {
    asm volatile("red.global.add.noftz.v2.f16x2 [%0], {%1,%2};"
                 :: "l"(p), "r"(a), "r"(b) : "memory");
}
__device__ __forceinline__ uint32_t pk2(__half a, __half b) {
    __half2 t = __halves2half2(a, b);
    return *reinterpret_cast<uint32_t*>(&t);
}
__device__ __forceinline__ uint32_t pkf2(float a, float b) {
    __half2 t = __floats2half2_rn(a, b);
    return *reinterpret_cast<uint32_t*>(&t);
}

// ---------------- K_pre: pack W hi/lo (tiny) ----------------
__global__ void k_pre(const float* __restrict__ W) {
    int t = blockIdx.x * blockDim.x + threadIdx.x;   // 16384 threads
    if (t < 16384) {
        int k = t >> 7, n = t & 127;          // W[k][n]
        float w = W[t];
        __half wh = __float2half_rn(w);
        __half wl = __float2half_rn(w - __half2float(wh));
        int s = k >> 4, kr = k & 15;
        int r = kr >> 3;
        int lane = ((n & 7) << 2) | ((kr & 7) >> 1);
        int j = n >> 3;
        int idx = ((((s * 16 + j) * 32 + lane) * 2 + r) << 1) | (kr & 1);
        g_Wph[idx] = wh;
        g_Wpl[idx] = wl;
    }
}

// ---------------- K1: Y = X@W + b; hi pass fp32-acc, corrections fp16-acc ----------------
#define SM_B    512
#define SM_A    (512 + 65536)
#define WREG    8704
#define SMEM_SZ (SM_A + 8 * WREG)

__global__ __launch_bounds__(256) void k_gemm(const float* __restrict__ X,
                                              const float* __restrict__ bbias) {
    extern __shared__ char smem[];
    float* bsm = reinterpret_cast<float*>(smem);
    uint2* Bsm = reinterpret_cast<uint2*>(smem + SM_B);

    const int tid  = threadIdx.x;
    const int wid  = tid >> 5, lane = tid & 31;
    const int row0 = blockIdx.x * 128;
    const int wrow0 = row0 + wid * 16;

    float4 xr[16];
    #pragma unroll
    for (int i = 0; i < 16; ++i) {
        xr[i] = make_float4(0.f, 0.f, 0.f, 0.f);
        if (wrow0 + i < NV)
            xr[i] = reinterpret_cast<const float4*>(X + (size_t)(wrow0 + i) * 128)[lane];
    }
    if (tid < 128) bsm[tid] = bbias[tid];

    {
        const uint4* sh = reinterpret_cast<const uint4*>(g_Wph);
        const uint4* sl = reinterpret_cast<const uint4*>(g_Wpl);
        uint4* dst = reinterpret_cast<uint4*>(Bsm);
        #pragma unroll
        for (int i = 0; i < 8; ++i) {
            dst[tid + i * 256]        = sh[tid + i * 256];
            dst[2048 + tid + i * 256] = sl[tid + i * 256];
        }
    }
    __syncthreads();

    __half* Aw = reinterpret_cast<__half*>(smem + SM_A + wid * WREG);
    #pragma unroll
    for (int i = 0; i < 16; ++i) {
        float4 x = xr[i];
        __half hx = __float2half_rn(x.x), hy = __float2half_rn(x.y);
        __half hz = __float2half_rn(x.z), hw = __float2half_rn(x.w);
        *reinterpret_cast<uint2*>(&Aw[i * ASTRIDE + lane * 4]) =
            make_uint2(pk2(hx, hy), pk2(hz, hw));
        *reinterpret_cast<uint2*>(&Aw[2176 + i * ASTRIDE + lane * 4]) =
            make_uint2(pk2(__float2half_rn(x.x - __half2float(hx)),
                           __float2half_rn(x.y - __half2float(hy))),
                       pk2(__float2half_rn(x.z - __half2float(hz)),
                           __float2half_rn(x.w - __half2float(hw))));
    }
    __syncwarp();

    const int rr = lane >> 2, kc = lane & 3;

    // pass 0: Ah x Bh, fp32 accumulate
    float acc[16][4];
    #pragma unroll
    for (int j = 0; j < 16; ++j)
        acc[j][0] = acc[j][1] = acc[j][2] = acc[j][3] = 0.f;
    #pragma unroll
    for (int s = 0; s < 8; ++s) {
        const int ka = s * 16 + kc * 2;
        uint32_t a0 = *reinterpret_cast<const uint32_t*>(&Aw[rr       * ASTRIDE + ka]);
        uint32_t a1 = *reinterpret_cast<const uint32_t*>(&Aw[(rr + 8) * ASTRIDE + ka]);
        uint32_t a2 = *reinterpret_cast<const uint32_t*>(&Aw[rr       * ASTRIDE + ka + 8]);
        uint32_t a3 = *reinterpret_cast<const uint32_t*>(&Aw[(rr + 8) * ASTRIDE + ka + 8]);
        #pragma unroll
        for (int j = 0; j < 16; ++j) {
            uint2 bb = Bsm[(s * 16 + j) * 32 + lane];
            asm volatile(
                "mma.sync.aligned.m16n8k16.row.col.f32.f16.f16.f32 "
                "{%0,%1,%2,%3}, {%4,%5,%6,%7}, {%8,%9}, {%0,%1,%2,%3};"
                : "+f"(acc[j][0]), "+f"(acc[j][1]), "+f"(acc[j][2]), "+f"(acc[j][3])
                : "r"(a0), "r"(a1), "r"(a2), "r"(a3), "r"(bb.x), "r"(bb.y));
        }
    }

    // passes 1+2: corrections, fp16 accumulate (shared hacc)
    uint32_t hacc[16][2];
    #pragma unroll
    for (int j = 0; j < 16; ++j) { hacc[j][0] = 0u; hacc[j][1] = 0u; }
    #pragma unroll 1
    for (int pass = 1; pass < 3; ++pass) {
        const __half* A = Aw + ((pass == 2) ? 2176 : 0);
        const uint2*  B = Bsm + ((pass == 1) ? 4096 : 0);
        #pragma unroll
        for (int s = 0; s < 8; ++s) {
            const int ka = s * 16 + kc * 2;
            uint32_t a0 = *reinterpret_cast<const uint32_t*>(&A[rr       * ASTRIDE + ka]);
            uint32_t a1 = *reinterpret_cast<const uint32_t*>(&A[(rr + 8) * ASTRIDE + ka]);
            uint32_t a2 = *reinterpret_cast<const uint32_t*>(&A[rr       * ASTRIDE + ka + 8]);
            uint32_t a3 = *reinterpret_cast<const uint32_t*>(&A[(rr + 8) * ASTRIDE + ka + 8]);
            #pragma unroll
            for (int j = 0; j < 16; ++j) {
                uint2 bb = B[(s * 16 + j) * 32 + lane];
                asm volatile(
                    "mma.sync.aligned.m16n8k16.row.col.f16.f16.f16.f16 "
                    "{%0,%1}, {%2,%3,%4,%5}, {%6,%7}, {%0,%1};"
                    : "+r"(hacc[j][0]), "+r"(hacc[j][1])
                    : "r"(a0), "r"(a1), "r"(a2), "r"(a3), "r"(bb.x), "r"(bb.y));
            }
        }
    }
    __syncwarp();

    float* stw = reinterpret_cast<float*>(smem + SM_A + wid * WREG);
    #pragma unroll
    for (int j = 0; j < 16; ++j) {
        const int n0 = j * 8 + kc * 2;
        const float b0 = bsm[n0], b1 = bsm[n0 + 1];
        float2 c01 = __half22float2(*reinterpret_cast<__half2*>(&hacc[j][0]));
        float2 c23 = __half22float2(*reinterpret_cast<__half2*>(&hacc[j][1]));
        *reinterpret_cast<float2*>(&stw[rr * 132 + n0]) =
            make_float2(acc[j][0] + c01.x + b0, acc[j][1] + c01.y + b1);
        *reinterpret_cast<float2*>(&stw[(rr + 8) * 132 + n0]) =
            make_float2(acc[j][2] + c23.x + b0, acc[j][3] + c23.y + b1);
    }
    __syncwarp();
    if (lane == 0) {
        #pragma unroll
        for (int r = 0; r < 16; ++r)
            if (wrow0 + r < NV) g_deg[wrow0 + r] = 1.0f;
    }
    #pragma unroll
    for (int r = 0; r < 16; ++r) {
        if (wrow0 + r < NV) {
            float4 v = *reinterpret_cast<const float4*>(&stw[r * 132 + lane * 4]);
            uint32_t h01 = pkf2(v.x, v.y), h23 = pkf2(v.z, v.w);
            float2 d01 = __half22float2(*reinterpret_cast<__half2*>(&h01));
            float2 d23 = __half22float2(*reinterpret_cast<__half2*>(&h23));
            const size_t o = (size_t)(wrow0 + r) * 128 + lane * 4;
            *reinterpret_cast<uint2*>(g_Yh + o) = make_uint2(h01, h23);
            *reinterpret_cast<uint2*>(g_Yl + o) =
                make_uint2(pkf2(v.x - d01.x, v.y - d01.y), pkf2(v.z - d23.x, v.w - d23.y));
            *reinterpret_cast<uint2*>(g_acc + o) = make_uint2(0u, 0u);
        }
    }
}

// ---------------- K2: per-hyperedge argmax pair via mma Gram + degree atomics ----------------
__global__ __launch_bounds__(256) void k_edges(const int* __restrict__ vertex) {
    __shared__ __half sF[8][2][8][ASTRIDE];
    const int wip  = threadIdx.x >> 5;
    const int warp = blockIdx.x * 8 + wip;
    const int lane = threadIdx.x & 31;
    if (warp >= ME) return;
    const unsigned FULL = 0xffffffffu;

    int vr = (lane < KH) ? vertex[warp * KH + lane] : 0;
    int verts[KH];
    #pragma unroll
    for (int i = 0; i < KH; ++i) verts[i] = __shfl_sync(FULL, vr, i);

    #pragma unroll
    for (int k = 0; k < KH; ++k) {
        const size_t o = (size_t)verts[k] * DD + lane * 4;
        *reinterpret_cast<uint2*>(&sF[wip][0][k][lane * 4]) =
            *reinterpret_cast<const uint2*>(g_Yh + o);
        *reinterpret_cast<uint2*>(&sF[wip][1][k][lane * 4]) =
            *reinterpret_cast<const uint2*>(g_Yl + o);
    }
    __syncwarp();

    const int rr = lane >> 2, kc = lane & 3;
    float c0 = 0.f, c1 = 0.f, c2 = 0.f, c3 = 0.f;
    #pragma unroll
    for (int s = 0; s < 8; ++s) {
        const int ka = s * 16 + kc * 2;
        uint32_t h0 = *reinterpret_cast<const uint32_t*>(&sF[wip][0][rr][ka]);
        uint32_t h1 = *reinterpret_cast<const uint32_t*>(&sF[wip][0][rr][ka + 8]);
        uint32_t l0 = *reinterpret_cast<const uint32_t*>(&sF[wip][1][rr][ka]);
        uint32_t l1 = *reinterpret_cast<const uint32_t*>(&sF[wip][1][rr][ka + 8]);
        asm volatile("mma.sync.aligned.m16n8k16.row.col.f32.f16.f16.f32 "
            "{%0,%1,%2,%3}, {%4,%5,%6,%7}, {%8,%9}, {%0,%1,%2,%3};"
            : "+f"(c0), "+f"(c1), "+f"(c2), "+f"(c3)
            : "r"(h0), "r"(0u), "r"(h1), "r"(0u), "r"(h0), "r"(h1));
        asm volatile("mma.sync.aligned.m16n8k16.row.col.f32.f16.f16.f32 "
            "{%0,%1,%2,%3}, {%4,%5,%6,%7}, {%8,%9}, {%0,%1,%2,%3};"
            : "+f"(c0), "+f"(c1), "+f"(c2), "+f"(c3)
            : "r"(h0), "r"(0u), "r"(h1), "r"(0u), "r"(l0), "r"(l1));
        asm volatile("mma.sync.aligned.m16n8k16.row.col.f32.f16.f16.f32 "
            "{%0,%1,%2,%3}, {%4,%5,%6,%7}, {%8,%9}, {%0,%1,%2,%3};"
            : "+f"(c0), "+f"(c1), "+f"(c2), "+f"(c3)
            : "r"(l0), "r"(0u), "r"(l1), "r"(0u), "r"(h0), "r"(h1));
    }

    const float mydiag = (rr & 1) ? c1 : c0;
    const float sq_r  = __shfl_sync(FULL, mydiag, rr * 4 + (rr >> 1));
    const float sq_c0 = __shfl_sync(FULL, mydiag, 9 * kc);
    const float sq_c1 = __shfl_sync(FULL, mydiag, 9 * kc + 4);

    float e0 = (sq_r + sq_c0) - 2.0f * c0;
    float e1 = (sq_r + sq_c1) - 2.0f * c1;
    int   i0 = rr * 8 + kc * 2;
    float bv; int bi;
    if (e1 > e0) { bv = e1; bi = i0 + 1; } else { bv = e0; bi = i0; }
    #pragma unroll
    for (int s = 16; s > 0; s >>= 1) {
        float ov = __shfl_xor_sync(FULL, bv, s);
        int   oi = __shfl_xor_sync(FULL, bi, s);
        if (ov > bv || (ov == bv && oi < bi)) { bv = ov; bi = oi; }
    }
    const int ui = bi >> 3, vi = bi & 7;

    if (lane == 0) g_pos[warp] = ui | (vi << 8);
    const float w = 1.0f / 13.0f;
    if (lane < KH) {
        if (lane == ui)       atomicAdd(&g_deg[verts[ui]], 7.0f * w);
        else if (lane == vi)  atomicAdd(&g_deg[verts[vi]], 7.0f * w);
        else                  atomicAdd(&g_deg[verts[lane]], 2.0f * w);
    }
}

// ---------------- K4: scatter — fp32 math, fp16 v2.f16x2 reds into g_acc ----------------
__global__ __launch_bounds__(256) void k_scatter(const int* __restrict__ vertex) {
    const int warp = (blockIdx.x * 256 + threadIdx.x) >> 5;
    const int lane = threadIdx.x & 31;
    if (warp >= ME) return;
    const unsigned FULL = 0xffffffffu;

    int   vr = (lane < KH) ? vertex[warp * KH + lane] : 0;
    float dr = (lane < KH) ? rsqrtf(g_deg[vr]) : 0.f;
    int verts[KH];
    float dk[KH];
    #pragma unroll
    for (int i = 0; i < KH; ++i) {
        verts[i] = __shfl_sync(FULL, vr, i);
        dk[i]    = __shfl_sync(FULL, dr, i);
    }

    uint2 h[KH];
    #pragma unroll
    for (int k = 0; k < KH; ++k)
        h[k] = *reinterpret_cast<const uint2*>(g_Yh + (size_t)verts[k] * DD + lane * 4);

    const int pos = g_pos[warp];
    const int ui = pos & 0xff, vi = (pos >> 8) & 0xff;
    const int u = verts[ui], v = verts[vi];
    const float w = 1.0f / 13.0f;

    float4 xu = make_float4(0.f, 0.f, 0.f, 0.f), xv = xu;
    #pragma unroll
    for (int k = 0; k < KH; ++k) {
        float2 a = __half22float2(*reinterpret_cast<__half2*>(&h[k].x));
        float2 bq = __half22float2(*reinterpret_cast<__half2*>(&h[k].y));
        const float d = dk[k];
        float4 f = make_float4(a.x * d, a.y * d, bq.x * d, bq.y * d);
        if (k == ui) xu = f;
        if (k == vi) xv = f;
    }

    const uint32_t t01 = pkf2(w * (xu.x + xv.x), w * (xu.y + xv.y));
    const uint32_t t23 = pkf2(w * (xu.z + xv.z), w * (xu.w + xv.w));

    float4 S = make_float4(0.f, 0.f, 0.f, 0.f);
    #pragma unroll
    for (int k = 0; k < KH; ++k) {
        if (k == ui || k == vi) continue;
        float2 a = __half22float2(*reinterpret_cast<__half2*>(&h[k].x));
        float2 bq = __half22float2(*reinterpret_cast<__half2*>(&h[k].y));
        const float d = dk[k];
        S.x += a.x * d; S.y += a.y * d; S.z += bq.x * d; S.w += bq.y * d;
        red2h(g_acc + (size_t)verts[k] * DD + lane * 4, t01, t23);
    }
    red2h(g_acc + (size_t)u * DD + lane * 4,
          pkf2(w * (xv.x + S.x), w * (xv.y + S.y)),
          pkf2(w * (xv.z + S.z), w * (xv.w + S.w)));
    red2h(g_acc + (size_t)v * DD + lane * 4,
          pkf2(w * (xu.x + S.x), w * (xu.y + S.y)),
          pkf2(w * (xu.z + S.z), w * (xu.w + S.w)));
}

// ---------------- K5: out = relu(dinv*(dinv*hi + acc)) ----------------
__global__ void k_fin(float* __restrict__ out) {
    int i = blockIdx.x * blockDim.x + threadIdx.x;   // float4 idx, < NV*32
    const int n = i >> 5;
    const float d = rsqrtf(g_deg[n]);
    uint2 hvv = reinterpret_cast<const uint2*>(g_Yh)[i];
    uint2 avv = reinterpret_cast<const uint2*>(g_acc)[i];
    float2 h01 = __half22float2(*reinterpret_cast<__half2*>(&hvv.x));
    float2 h23 = __half22float2(*reinterpret_cast<__half2*>(&hvv.y));
    float2 a01 = __half22float2(*reinterpret_cast<__half2*>(&avv.x));
    float2 a23 = __half22float2(*reinterpret_cast<__half2*>(&avv.y));
    float4 o;
    o.x = fmaxf(d * (d * h01.x + a01.x), 0.f);
    o.y = fmaxf(d * (d * h01.y + a01.y), 0.f);
    o.z = fmaxf(d * (d * h23.x + a23.x), 0.f);
    o.w = fmaxf(d * (d * h23.y + a23.y), 0.f);
    reinterpret_cast<float4*>(out)[i] = o;
}

// ---------------- launch ----------------
extern "C" void kernel_launch(void* const* d_in, const int* in_sizes, int n_in,
                              void* d_out, int out_size) {
    const float* X      = (const float*)d_in[0];   // [N, 128]
    const int*   vertex = (const int*)  d_in[1];   // [M*8]
    const float* W      = (const float*)d_in[3];   // [128, 128]
    const float* b      = (const float*)d_in[4];   // [128]
    float* out = (float*)d_out;

    cudaFuncSetAttribute(k_gemm, cudaFuncAttributeMaxDynamicSharedMemorySize, SMEM_SZ);

    k_pre<<<64, 256>>>(W);
    k_gemm<<<(NV + 127) / 128, 256, SMEM_SZ>>>(X, b);
    k_edges<<<(ME + 7) / 8, 256>>>(vertex);
    k_scatter<<<(ME * 32 + 255) / 256, 256>>>(vertex);
    k_fin<<<NV * 32 / 256, 256>>>(out);
}

// round 17
// speedup vs baseline: 1.0073x; 1.0073x over previous
#include <cuda_runtime.h>
#include <cuda_fp16.h>
#include <cstdint>

#define NV 100000      // vertices
#define ME 50000       // hyperedges
#define KH 8           // hyperedge size
#define DD 128         // feature dim
#define ASTRIDE 136    // smem A row stride (halves)

// ---------------- scratch (no allocs allowed) ----------------
__device__ __half g_Yh [(size_t)NV * DD];   // Y hi (fp16)
__device__ __half g_Yl [(size_t)NV * DD];   // Y lo (fp16 residual)
__device__ __half g_acc[(size_t)NV * DD];   // fp16 neighbor accumulator
__device__ float  g_deg [NV];
__device__ int    g_pos[ME];                // ui | (vi<<8)
__device__ __half g_Wph[16384];             // W hi, mma B-fragment layout
__device__ __half g_Wpl[16384];             // W lo, mma B-fragment layout

__device__ __forceinline__ void red2h(__half* p, uint32_t a, uint32_t b) {
    asm volatile("red.global.add.noftz.v2.f16x2 [%0], {%1,%2};"
                 :: "l"(p), "r"(a), "r"(b) : "memory");
}
__device__ __forceinline__ uint32_t pk2(__half a, __half b) {
    __half2 t = __halves2half2(a, b);
    return *reinterpret_cast<uint32_t*>(&t);
}
__device__ __forceinline__ uint32_t pkf2(float a, float b) {
    __half2 t = __floats2half2_rn(a, b);
    return *reinterpret_cast<uint32_t*>(&t);
}

// ---------------- K_pre: pack W hi/lo (tiny) ----------------
__global__ void k_pre(const float* __restrict__ W) {
    int t = blockIdx.x * blockDim.x + threadIdx.x;   // 16384 threads
    if (t < 16384) {
        int k = t >> 7, n = t & 127;          // W[k][n]
        float w = W[t];
        __half wh = __float2half_rn(w);
        __half wl = __float2half_rn(w - __half2float(wh));
        int s = k >> 4, kr = k & 15;
        int r = kr >> 3;
        int lane = ((n & 7) << 2) | ((kr & 7) >> 1);
        int j = n >> 3;
        int idx = ((((s * 16 + j) * 32 + lane) * 2 + r) << 1) | (kr & 1);
        g_Wph[idx] = wh;
        g_Wpl[idx] = wl;
    }
}

// ---------------- K1: Y = X@W + b; fused 3-in-1 mainloop (B loaded 2x not 3x) ----------------
#define SM_B    512
#define SM_A    (512 + 65536)
#define WREG    8704
#define SMEM_SZ (SM_A + 8 * WREG)

__global__ __launch_bounds__(256) void k_gemm(const float* __restrict__ X,
                                              const float* __restrict__ bbias) {
    extern __shared__ char smem[];
    float* bsm = reinterpret_cast<float*>(smem);
    uint2* Bsm = reinterpret_cast<uint2*>(smem + SM_B);

    const int tid  = threadIdx.x;
    const int wid  = tid >> 5, lane = tid & 31;
    const int row0 = blockIdx.x * 128;
    const int wrow0 = row0 + wid * 16;

    float4 xr[16];
    #pragma unroll
    for (int i = 0; i < 16; ++i) {
        xr[i] = make_float4(0.f, 0.f, 0.f, 0.f);
        if (wrow0 + i < NV)
            xr[i] = reinterpret_cast<const float4*>(X + (size_t)(wrow0 + i) * 128)[lane];
    }
    if (tid < 128) bsm[tid] = bbias[tid];

    {
        const uint4* sh = reinterpret_cast<const uint4*>(g_Wph);
        const uint4* sl = reinterpret_cast<const uint4*>(g_Wpl);
        uint4* dst = reinterpret_cast<uint4*>(Bsm);
        #pragma unroll
        for (int i = 0; i < 8; ++i) {
            dst[tid + i * 256]        = sh[tid + i * 256];
            dst[2048 + tid + i * 256] = sl[tid + i * 256];
        }
    }
    __syncthreads();

    __half* Aw = reinterpret_cast<__half*>(smem + SM_A + wid * WREG);
    #pragma unroll
    for (int i = 0; i < 16; ++i) {
        float4 x = xr[i];
        __half hx = __float2half_rn(x.x), hy = __float2half_rn(x.y);
        __half hz = __float2half_rn(x.z), hw = __float2half_rn(x.w);
        *reinterpret_cast<uint2*>(&Aw[i * ASTRIDE + lane * 4]) =
            make_uint2(pk2(hx, hy), pk2(hz, hw));
        *reinterpret_cast<uint2*>(&Aw[2176 + i * ASTRIDE + lane * 4]) =
            make_uint2(pk2(__float2half_rn(x.x - __half2float(hx)),
                           __float2half_rn(x.y - __half2float(hy))),
                       pk2(__float2half_rn(x.z - __half2float(hz)),
                           __float2half_rn(x.w - __half2float(hw))));
    }
    __syncwarp();

    const int rr = lane >> 2, kc = lane & 3;

    float acc[16][4];
    uint32_t hacc[16][2];
    #pragma unroll
    for (int j = 0; j < 16; ++j) {
        acc[j][0] = acc[j][1] = acc[j][2] = acc[j][3] = 0.f;
        hacc[j][0] = 0u; hacc[j][1] = 0u;
    }

    // fused mainloop: per s load Ah+Al frags once; per (s,j) load bh+bl once, 3 MMAs
    #pragma unroll
    for (int s = 0; s < 8; ++s) {
        const int ka = s * 16 + kc * 2;
        uint32_t ah0 = *reinterpret_cast<const uint32_t*>(&Aw[rr       * ASTRIDE + ka]);
        uint32_t ah1 = *reinterpret_cast<const uint32_t*>(&Aw[(rr + 8) * ASTRIDE + ka]);
        uint32_t ah2 = *reinterpret_cast<const uint32_t*>(&Aw[rr       * ASTRIDE + ka + 8]);
        uint32_t ah3 = *reinterpret_cast<const uint32_t*>(&Aw[(rr + 8) * ASTRIDE + ka + 8]);
        uint32_t al0 = *reinterpret_cast<const uint32_t*>(&Aw[2176 + rr       * ASTRIDE + ka]);
        uint32_t al1 = *reinterpret_cast<const uint32_t*>(&Aw[2176 + (rr + 8) * ASTRIDE + ka]);
        uint32_t al2 = *reinterpret_cast<const uint32_t*>(&Aw[2176 + rr       * ASTRIDE + ka + 8]);
        uint32_t al3 = *reinterpret_cast<const uint32_t*>(&Aw[2176 + (rr + 8) * ASTRIDE + ka + 8]);
        #pragma unroll
        for (int j = 0; j < 16; ++j) {
            uint2 bh = Bsm[(s * 16 + j) * 32 + lane];
            uint2 bl = Bsm[4096 + (s * 16 + j) * 32 + lane];
            asm volatile(
                "mma.sync.aligned.m16n8k16.row.col.f32.f16.f16.f32 "
                "{%0,%1,%2,%3}, {%4,%5,%6,%7}, {%8,%9}, {%0,%1,%2,%3};"
                : "+f"(acc[j][0]), "+f"(acc[j][1]), "+f"(acc[j][2]), "+f"(acc[j][3])
                : "r"(ah0), "r"(ah1), "r"(ah2), "r"(ah3), "r"(bh.x), "r"(bh.y));
            asm volatile(
                "mma.sync.aligned.m16n8k16.row.col.f16.f16.f16.f16 "
                "{%0,%1}, {%2,%3,%4,%5}, {%6,%7}, {%0,%1};"
                : "+r"(hacc[j][0]), "+r"(hacc[j][1])
                : "r"(ah0), "r"(ah1), "r"(ah2), "r"(ah3), "r"(bl.x), "r"(bl.y));
            asm volatile(
                "mma.sync.aligned.m16n8k16.row.col.f16.f16.f16.f16 "
                "{%0,%1}, {%2,%3,%4,%5}, {%6,%7}, {%0,%1};"
                : "+r"(hacc[j][0]), "+r"(hacc[j][1])
                : "r"(al0), "r"(al1), "r"(al2), "r"(al3), "r"(bh.x), "r"(bh.y));
        }
    }
    __syncwarp();

    float* stw = reinterpret_cast<float*>(smem + SM_A + wid * WREG);
    #pragma unroll
    for (int j = 0; j < 16; ++j) {
        const int n0 = j * 8 + kc * 2;
        const float b0 = bsm[n0], b1 = bsm[n0 + 1];
        float2 c01 = __half22float2(*reinterpret_cast<__half2*>(&hacc[j][0]));
        float2 c23 = __half22float2(*reinterpret_cast<__half2*>(&hacc[j][1]));
        *reinterpret_cast<float2*>(&stw[rr * 132 + n0]) =
            make_float2(acc[j][0] + c01.x + b0, acc[j][1] + c01.y + b1);
        *reinterpret_cast<float2*>(&stw[(rr + 8) * 132 + n0]) =
            make_float2(acc[j][2] + c23.x + b0, acc[j][3] + c23.y + b1);
    }
    __syncwarp();
    if (lane == 0) {
        #pragma unroll
        for (int r = 0; r < 16; ++r)
            if (wrow0 + r < NV) g_deg[wrow0 + r] = 1.0f;
    }
    #pragma unroll
    for (int r = 0; r < 16; ++r) {
        if (wrow0 + r < NV) {
            float4 v = *reinterpret_cast<const float4*>(&stw[r * 132 + lane * 4]);
            uint32_t h01 = pkf2(v.x, v.y), h23 = pkf2(v.z, v.w);
            float2 d01 = __half22float2(*reinterpret_cast<__half2*>(&h01));
            float2 d23 = __half22float2(*reinterpret_cast<__half2*>(&h23));
            const size_t o = (size_t)(wrow0 + r) * 128 + lane * 4;
            *reinterpret_cast<uint2*>(g_Yh + o) = make_uint2(h01, h23);
            *reinterpret_cast<uint2*>(g_Yl + o) =
                make_uint2(pkf2(v.x - d01.x, v.y - d01.y), pkf2(v.z - d23.x, v.w - d23.y));
            *reinterpret_cast<uint2*>(g_acc + o) = make_uint2(0u, 0u);
        }
    }
}

// ---------------- K2: per-hyperedge argmax pair via mma Gram + degree atomics ----------------
__global__ __launch_bounds__(256) void k_edges(const int* __restrict__ vertex) {
    __shared__ __half sF[8][2][8][ASTRIDE];
    const int wip  = threadIdx.x >> 5;
    const int warp = blockIdx.x * 8 + wip;
    const int lane = threadIdx.x & 31;
    if (warp >= ME) return;
    const unsigned FULL = 0xffffffffu;

    int vr = (lane < KH) ? vertex[warp * KH + lane] : 0;
    int verts[KH];
    #pragma unroll
    for (int i = 0; i < KH; ++i) verts[i] = __shfl_sync(FULL, vr, i);

    #pragma unroll
    for (int k = 0; k < KH; ++k) {
        const size_t o = (size_t)verts[k] * DD + lane * 4;
        *reinterpret_cast<uint2*>(&sF[wip][0][k][lane * 4]) =
            *reinterpret_cast<const uint2*>(g_Yh + o);
        *reinterpret_cast<uint2*>(&sF[wip][1][k][lane * 4]) =
            *reinterpret_cast<const uint2*>(g_Yl + o);
    }
    __syncwarp();

    const int rr = lane >> 2, kc = lane & 3;
    float c0 = 0.f, c1 = 0.f, c2 = 0.f, c3 = 0.f;
    #pragma unroll
    for (int s = 0; s < 8; ++s) {
        const int ka = s * 16 + kc * 2;
        uint32_t h0 = *reinterpret_cast<const uint32_t*>(&sF[wip][0][rr][ka]);
        uint32_t h1 = *reinterpret_cast<const uint32_t*>(&sF[wip][0][rr][ka + 8]);
        uint32_t l0 = *reinterpret_cast<const uint32_t*>(&sF[wip][1][rr][ka]);
        uint32_t l1 = *reinterpret_cast<const uint32_t*>(&sF[wip][1][rr][ka + 8]);
        asm volatile("mma.sync.aligned.m16n8k16.row.col.f32.f16.f16.f32 "
            "{%0,%1,%2,%3}, {%4,%5,%6,%7}, {%8,%9}, {%0,%1,%2,%3};"
            : "+f"(c0), "+f"(c1), "+f"(c2), "+f"(c3)
            : "r"(h0), "r"(0u), "r"(h1), "r"(0u), "r"(h0), "r"(h1));
        asm volatile("mma.sync.aligned.m16n8k16.row.col.f32.f16.f16.f32 "
            "{%0,%1,%2,%3}, {%4,%5,%6,%7}, {%8,%9}, {%0,%1,%2,%3};"
            : "+f"(c0), "+f"(c1), "+f"(c2), "+f"(c3)
            : "r"(h0), "r"(0u), "r"(h1), "r"(0u), "r"(l0), "r"(l1));
        asm volatile("mma.sync.aligned.m16n8k16.row.col.f32.f16.f16.f32 "
            "{%0,%1,%2,%3}, {%4,%5,%6,%7}, {%8,%9}, {%0,%1,%2,%3};"
            : "+f"(c0), "+f"(c1), "+f"(c2), "+f"(c3)
            : "r"(l0), "r"(0u), "r"(l1), "r"(0u), "r"(h0), "r"(h1));
    }

    const float mydiag = (rr & 1) ? c1 : c0;
    const float sq_r  = __shfl_sync(FULL, mydiag, rr * 4 + (rr >> 1));
    const float sq_c0 = __shfl_sync(FULL, mydiag, 9 * kc);
    const float sq_c1 = __shfl_sync(FULL, mydiag, 9 * kc + 4);

    float e0 = (sq_r + sq_c0) - 2.0f * c0;
    float e1 = (sq_r + sq_c1) - 2.0f * c1;
    int   i0 = rr * 8 + kc * 2;
    float bv; int bi;
    if (e1 > e0) { bv = e1; bi = i0 + 1; } else { bv = e0; bi = i0; }
    #pragma unroll
    for (int s = 16; s > 0; s >>= 1) {
        float ov = __shfl_xor_sync(FULL, bv, s);
        int   oi = __shfl_xor_sync(FULL, bi, s);
        if (ov > bv || (ov == bv && oi < bi)) { bv = ov; bi = oi; }
    }
    const int ui = bi >> 3, vi = bi & 7;

    if (lane == 0) g_pos[warp] = ui | (vi << 8);
    const float w = 1.0f / 13.0f;
    if (lane < KH) {
        if (lane == ui)       atomicAdd(&g_deg[verts[ui]], 7.0f * w);
        else if (lane == vi)  atomicAdd(&g_deg[verts[vi]], 7.0f * w);
        else                  atomicAdd(&g_deg[verts[lane]], 2.0f * w);
    }
}

// ---------------- K4: scatter — fp32 math, fp16 v2.f16x2 reds into g_acc ----------------
__global__ __launch_bounds__(256) void k_scatter(const int* __restrict__ vertex) {
    const int warp = (blockIdx.x * 256 + threadIdx.x) >> 5;
    const int lane = threadIdx.x & 31;
    if (warp >= ME) return;
    const unsigned FULL = 0xffffffffu;

    int   vr = (lane < KH) ? vertex[warp * KH + lane] : 0;
    float dr = (lane < KH) ? rsqrtf(g_deg[vr]) : 0.f;
    int verts[KH];
    float dk[KH];
    #pragma unroll
    for (int i = 0; i < KH; ++i) {
        verts[i] = __shfl_sync(FULL, vr, i);
        dk[i]    = __shfl_sync(FULL, dr, i);
    }

    uint2 h[KH];
    #pragma unroll
    for (int k = 0; k < KH; ++k)
        h[k] = *reinterpret_cast<const uint2*>(g_Yh + (size_t)verts[k] * DD + lane * 4);

    const int pos = g_pos[warp];
    const int ui = pos & 0xff, vi = (pos >> 8) & 0xff;
    const int u = verts[ui], v = verts[vi];
    const float w = 1.0f / 13.0f;

    float4 xu = make_float4(0.f, 0.f, 0.f, 0.f), xv = xu;
    #pragma unroll
    for (int k = 0; k < KH; ++k) {
        float2 a = __half22float2(*reinterpret_cast<__half2*>(&h[k].x));
        float2 bq = __half22float2(*reinterpret_cast<__half2*>(&h[k].y));
        const float d = dk[k];
        float4 f = make_float4(a.x * d, a.y * d, bq.x * d, bq.y * d);
        if (k == ui) xu = f;
        if (k == vi) xv = f;
    }

    const uint32_t t01 = pkf2(w * (xu.x + xv.x), w * (xu.y + xv.y));
    const uint32_t t23 = pkf2(w * (xu.z + xv.z), w * (xu.w + xv.w));

    float4 S = make_float4(0.f, 0.f, 0.f, 0.f);
    #pragma unroll
    for (int k = 0; k < KH; ++k) {
        if (k == ui || k == vi) continue;
        float2 a = __half22float2(*reinterpret_cast<__half2*>(&h[k].x));
        float2 bq = __half22float2(*reinterpret_cast<__half2*>(&h[k].y));
        const float d = dk[k];
        S.x += a.x * d; S.y += a.y * d; S.z += bq.x * d; S.w += bq.y * d;
        red2h(g_acc + (size_t)verts[k] * DD + lane * 4, t01, t23);
    }
    red2h(g_acc + (size_t)u * DD + lane * 4,
          pkf2(w * (xv.x + S.x), w * (xv.y + S.y)),
          pkf2(w * (xv.z + S.z), w * (xv.w + S.w)));
    red2h(g_acc + (size_t)v * DD + lane * 4,
          pkf2(w * (xu.x + S.x), w * (xu.y + S.y)),
          pkf2(w * (xu.z + S.z), w * (xu.w + S.w)));
}

// ---------------- K5: out = relu(dinv*(dinv*hi + acc)) ----------------
__global__ void k_fin(float* __restrict__ out) {
    int i = blockIdx.x * blockDim.x + threadIdx.x;   // float4 idx, < NV*32
    const int n = i >> 5;
    const float d = rsqrtf(g_deg[n]);
    uint2 hvv = reinterpret_cast<const uint2*>(g_Yh)[i];
    uint2 avv = reinterpret_cast<const uint2*>(g_acc)[i];
    float2 h01 = __half22float2(*reinterpret_cast<__half2*>(&hvv.x));
    float2 h23 = __half22float2(*reinterpret_cast<__half2*>(&hvv.y));
    float2 a01 = __half22float2(*reinterpret_cast<__half2*>(&avv.x));
    float2 a23 = __half22float2(*reinterpret_cast<__half2*>(&avv.y));
    float4 o;
    o.x = fmaxf(d * (d * h01.x + a01.x), 0.f);
    o.y = fmaxf(d * (d * h01.y + a01.y), 0.f);
    o.z = fmaxf(d * (d * h23.x + a23.x), 0.f);
    o.w = fmaxf(d * (d * h23.y + a23.y), 0.f);
    reinterpret_cast<float4*>(out)[i] = o;
}

// ---------------- launch ----------------
extern "C" void kernel_launch(void* const* d_in, const int* in_sizes, int n_in,
                              void* d_out, int out_size) {
    const float* X      = (const float*)d_in[0];   // [N, 128]
    const int*   vertex = (const int*)  d_in[1];   // [M*8]
    const float* W      = (const float*)d_in[3];   // [128, 128]
    const float* b      = (const float*)d_in[4];   // [128]
    float* out = (float*)d_out;

    cudaFuncSetAttribute(k_gemm, cudaFuncAttributeMaxDynamicSharedMemorySize, SMEM_SZ);

    k_pre<<<64, 256>>>(W);
    k_gemm<<<(NV + 127) / 128, 256, SMEM_SZ>>>(X, b);
    k_edges<<<(ME + 7) / 8, 256>>>(vertex);
    k_scatter<<<(ME * 32 + 255) / 256, 256>>>(vertex);
    k_fin<<<NV * 32 / 256, 256>>>(out);
}